// round 4
// baseline (speedup 1.0000x reference)
#include <cuda_runtime.h>
#include <math.h>
#include <float.h>

// ---------------------------------------------------------------------------
// Problem constants (fixed shapes)
// ---------------------------------------------------------------------------
#define BB   4
#define NY   16384
#define NX   4096
#define CY   128
#define CX   256
#define DIMC 384          // CY + CX
#define C1   512
#define C2   256
#define C3   128
#define NTOT (BB * NY)    // 65536
#define KNN_EPS 1e-8f
#define BN_EPS  1e-5f

#define NCHUNK 128
#define ROWS_PER_CHUNK (NTOT / NCHUNK)   // 512

// ---------------------------------------------------------------------------
// Device scratch: static __device__ arrays (allocation-free rule).
// ---------------------------------------------------------------------------
__device__ float g_X0[(size_t)NTOT * DIMC];
__device__ float g_H1[(size_t)NTOT * C1];
__device__ float g_H2[(size_t)NTOT * C2];
__device__ float g_H3[(size_t)NTOT * C3];
__device__ int   g_idx[NTOT * 3];
__device__ float g_w[NTOT * 3];
__device__ float g_psum[NCHUNK * C1];
__device__ float g_psq[NCHUNK * C1];
__device__ float g_scale[C1];
__device__ float g_shift[C1];

__device__ __forceinline__ float* pick_buf(int s) {
    switch (s) {
        case 0:  return g_X0;
        case 1:  return g_H1;
        case 2:  return g_H2;
        default: return g_H3;
    }
}

// ---------------------------------------------------------------------------
// KNN, bit-matching the reference numerics in fp32:
//   yn = (y0*y0 + y1*y1) + y2*y2            (rounded mul, linear sum, no fma)
//   xn = same
//   dot = fmaf(y2,x2, fmaf(y1,x1, rn(y0*x0)))   (cublas-style ascending-k FFMA)
//   d  = rn(rn(yn + xn) + rn(-2 * dot))
// Strict-< keeps earliest index on ties (top_k tie-break). One thread per
// y-point; Nx scanned in two 2048-point shared tiles of float4{x,y,z,xnorm}.
// ---------------------------------------------------------------------------
__global__ void knn_kernel(const float* __restrict__ yp,
                           const float* __restrict__ xp)
{
    __shared__ float4 sx[2048];   // 32 KB
    int b = blockIdx.y;
    const float* xb = xp + (size_t)b * NX * 3;

    int n = blockIdx.x * blockDim.x + threadIdx.x;
    const float* y = yp + ((size_t)b * NY + n) * 3;
    float yx = y[0], yy = y[1], yz = y[2];
    float yn = __fadd_rn(__fadd_rn(__fmul_rn(yx, yx), __fmul_rn(yy, yy)),
                         __fmul_rn(yz, yz));

    float d0 = FLT_MAX, d1 = FLT_MAX, d2 = FLT_MAX;
    int   i0 = 0, i1 = 0, i2 = 0;

    for (int t = 0; t < 2; t++) {
        __syncthreads();
        for (int i = threadIdx.x; i < 2048; i += blockDim.x) {
            const float* p = xb + (size_t)(t * 2048 + i) * 3;
            float a = p[0], c = p[1], e = p[2];
            float xn = __fadd_rn(__fadd_rn(__fmul_rn(a, a), __fmul_rn(c, c)),
                                 __fmul_rn(e, e));
            sx[i] = make_float4(a, c, e, xn);
        }
        __syncthreads();

        int base = t * 2048;
        #pragma unroll 4
        for (int j = 0; j < 2048; j++) {
            float4 q = sx[j];
            float dot = __fmaf_rn(yz, q.z,
                        __fmaf_rn(yy, q.y, __fmul_rn(yx, q.x)));
            float d = __fadd_rn(__fadd_rn(yn, q.w),
                                __fmul_rn(-2.0f, dot));
            if (d < d2) {
                int jj = base + j;
                if (d < d1) {
                    d2 = d1; i2 = i1;
                    if (d < d0) { d1 = d0; i1 = i0; d0 = d; i0 = jj; }
                    else        { d1 = d;  i1 = jj; }
                } else { d2 = d; i2 = jj; }
            }
        }
    }

    // w = 1/(d+eps); w /= sum(w)  — rounded divides, linear sum in rank order
    float w0 = __fdiv_rn(1.0f, __fadd_rn(d0, KNN_EPS));
    float w1 = __fdiv_rn(1.0f, __fadd_rn(d1, KNN_EPS));
    float w2 = __fdiv_rn(1.0f, __fadd_rn(d2, KNN_EPS));
    float ws = __fadd_rn(__fadd_rn(w0, w1), w2);

    size_t o = ((size_t)b * NY + n) * 3;
    g_idx[o + 0] = i0; g_idx[o + 1] = i1; g_idx[o + 2] = i2;
    g_w[o + 0] = __fdiv_rn(w0, ws);
    g_w[o + 1] = __fdiv_rn(w1, ws);
    g_w[o + 2] = __fdiv_rn(w2, ws);
}

// ---------------------------------------------------------------------------
// Interpolate + concat: one warp per y-point builds X0 row = [y_feats(128) |
// weighted sum of 3 gathered x_feats rows (256)]. Rounded mul/add in K order
// (matches sum(nb * w, axis=2) without fma contraction).
// ---------------------------------------------------------------------------
__global__ void interp_kernel(const float* __restrict__ yf,
                              const float* __restrict__ xf)
{
    int warp = (blockIdx.x * blockDim.x + threadIdx.x) >> 5;
    int lane = threadIdx.x & 31;
    if (warp >= NTOT) return;

    int b = warp / NY;
    size_t o = (size_t)warp * 3;
    int i0 = g_idx[o + 0], i1 = g_idx[o + 1], i2 = g_idx[o + 2];
    float w0 = g_w[o + 0], w1 = g_w[o + 1], w2 = g_w[o + 2];

    const float* f0 = xf + ((size_t)b * NX + i0) * CX;
    const float* f1 = xf + ((size_t)b * NX + i1) * CX;
    const float* f2 = xf + ((size_t)b * NX + i2) * CX;
    const float* yrow = yf + (size_t)warp * CY;
    float* row = g_X0 + (size_t)warp * DIMC;

    #pragma unroll
    for (int c = lane * 4; c < CY; c += 128)
        *(float4*)&row[c] = *(const float4*)&yrow[c];
    #pragma unroll
    for (int c = lane * 4; c < CX; c += 128) {
        float4 a = *(const float4*)&f0[c];
        float4 b4 = *(const float4*)&f1[c];
        float4 d = *(const float4*)&f2[c];
        float4 r;
        r.x = __fadd_rn(__fadd_rn(__fmul_rn(w0, a.x), __fmul_rn(w1, b4.x)), __fmul_rn(w2, d.x));
        r.y = __fadd_rn(__fadd_rn(__fmul_rn(w0, a.y), __fmul_rn(w1, b4.y)), __fmul_rn(w2, d.y));
        r.z = __fadd_rn(__fadd_rn(__fmul_rn(w0, a.z), __fmul_rn(w1, b4.z)), __fmul_rn(w2, d.z));
        r.w = __fadd_rn(__fadd_rn(__fmul_rn(w0, a.w), __fmul_rn(w1, b4.w)), __fmul_rn(w2, d.w));
        *(float4*)&row[CY + c] = r;
    }
}

// ---------------------------------------------------------------------------
// SGEMM with bias, exact fp32 (fma accumulate). Optionally fuses the PREVIOUS
// layer's BN+ReLU into the A-tile load.
// C[M,N] = A_eff[M,K] * W[N,K]^T + bias.  128x128x8 tiles, 256 thr, 8x8/thr.
// ---------------------------------------------------------------------------
template <bool FUSE_BN>
__global__ void __launch_bounds__(256)
sgemm_fused_kernel(int selA, int selC,
                   const float* __restrict__ W, const float* __restrict__ bias,
                   int K, int N)
{
    __shared__ float As[8][128];
    __shared__ float Bs[8][128];

    const float* A = pick_buf(selA);
    float* C = pick_buf(selC);

    int tid  = threadIdx.x;
    int row0 = blockIdx.x * 128;
    int col0 = blockIdx.y * 128;
    int lr = tid >> 1;            // 0..127
    int lc = (tid & 1) << 2;      // 0 or 4
    int ty = tid >> 4;            // 0..15
    int tx = tid & 15;            // 0..15

    const float* Ap = A + (size_t)(row0 + lr) * K + lc;
    const float* Wp = W + (size_t)(col0 + lr) * K + lc;

    float acc[8][8];
    #pragma unroll
    for (int i = 0; i < 8; i++)
        #pragma unroll
        for (int j = 0; j < 8; j++) acc[i][j] = 0.0f;

    for (int k0 = 0; k0 < K; k0 += 8) {
        float4 av = *(const float4*)(Ap + k0);
        if (FUSE_BN) {
            float4 sc = *(const float4*)&g_scale[k0 + lc];
            float4 sh = *(const float4*)&g_shift[k0 + lc];
            av.x = fmaxf(fmaf(av.x, sc.x, sh.x), 0.0f);
            av.y = fmaxf(fmaf(av.y, sc.y, sh.y), 0.0f);
            av.z = fmaxf(fmaf(av.z, sc.z, sh.z), 0.0f);
            av.w = fmaxf(fmaf(av.w, sc.w, sh.w), 0.0f);
        }
        float4 wv = *(const float4*)(Wp + k0);
        As[lc + 0][lr] = av.x; As[lc + 1][lr] = av.y;
        As[lc + 2][lr] = av.z; As[lc + 3][lr] = av.w;
        Bs[lc + 0][lr] = wv.x; Bs[lc + 1][lr] = wv.y;
        Bs[lc + 2][lr] = wv.z; Bs[lc + 3][lr] = wv.w;
        __syncthreads();

        #pragma unroll
        for (int kk = 0; kk < 8; kk++) {
            float4 a0 = *(const float4*)&As[kk][ty * 8];
            float4 a1 = *(const float4*)&As[kk][ty * 8 + 4];
            float4 b0 = *(const float4*)&Bs[kk][tx * 8];
            float4 b1 = *(const float4*)&Bs[kk][tx * 8 + 4];
            float a[8]  = {a0.x, a0.y, a0.z, a0.w, a1.x, a1.y, a1.z, a1.w};
            float bv[8] = {b0.x, b0.y, b0.z, b0.w, b1.x, b1.y, b1.z, b1.w};
            #pragma unroll
            for (int i = 0; i < 8; i++)
                #pragma unroll
                for (int j = 0; j < 8; j++)
                    acc[i][j] = fmaf(a[i], bv[j], acc[i][j]);
        }
        __syncthreads();
    }

    #pragma unroll
    for (int i = 0; i < 8; i++) {
        int r = row0 + ty * 8 + i;
        #pragma unroll
        for (int j = 0; j < 8; j += 4) {
            int c = col0 + tx * 8 + j;
            float4 v;
            v.x = acc[i][j + 0] + bias[c + 0];
            v.y = acc[i][j + 1] + bias[c + 1];
            v.z = acc[i][j + 2] + bias[c + 2];
            v.w = acc[i][j + 3] + bias[c + 3];
            *(float4*)&C[(size_t)r * N + c] = v;
        }
    }
}

// ---------------------------------------------------------------------------
// BN stage 1: deterministic per-chunk per-channel sum and sum-of-squares.
// ---------------------------------------------------------------------------
__global__ void colsum_kernel(int selH, int C)
{
    const float* H = pick_buf(selH);
    int c = threadIdx.x;
    int chunk = blockIdx.x;
    const float* p = H + (size_t)chunk * ROWS_PER_CHUNK * C;
    float s = 0.0f, ss = 0.0f;
    for (int r = 0; r < ROWS_PER_CHUNK; r++) {
        float v = p[(size_t)r * C + c];
        s += v; ss = fmaf(v, v, ss);
    }
    g_psum[chunk * C + c] = s;
    g_psq[chunk * C + c]  = ss;
}

// BN stage 2: finish mean/var, emit fused affine (scale, shift).
__global__ void bnstats_kernel(const float* __restrict__ g,
                               const float* __restrict__ be, int C)
{
    int c = threadIdx.x;
    float s = 0.0f, ss = 0.0f;
    for (int j = 0; j < NCHUNK; j++) {
        s += g_psum[j * C + c];
        ss += g_psq[j * C + c];
    }
    const float invN = 1.0f / (float)NTOT;
    float mu  = s * invN;
    float var = ss * invN - mu * mu;
    float inv = rsqrtf(var + BN_EPS);
    float a = g[c] * inv;
    g_scale[c] = a;
    g_shift[c] = be[c] - mu * a;
}

// ---------------------------------------------------------------------------
// Final: affine + ReLU + transpose [N, C3] -> [B, C3, NY], 32x32 smem tiles.
// ---------------------------------------------------------------------------
__global__ void final_kernel(float* __restrict__ out)
{
    __shared__ float tile[32][33];
    int nb = blockIdx.x;
    int cb = blockIdx.y;
    int lx = threadIdx.x;    // 32
    int ly = threadIdx.y;    // 8

    int c = cb * 32 + lx;
    float a = g_scale[c], sh = g_shift[c];
    #pragma unroll
    for (int s = 0; s < 4; s++) {
        int r = nb * 32 + ly + s * 8;
        float v = fmaf(g_H3[(size_t)r * C3 + c], a, sh);
        tile[ly + s * 8][lx] = fmaxf(v, 0.0f);
    }
    __syncthreads();

    int gn = nb * 32 + lx;
    int b  = gn / NY;
    int nn = gn % NY;
    #pragma unroll
    for (int s = 0; s < 4; s++) {
        int cc = cb * 32 + ly + s * 8;
        out[((size_t)b * C3 + cc) * NY + nn] = tile[lx][ly + s * 8];
    }
}

// ---------------------------------------------------------------------------
// Launch: kernel launches ONLY — no runtime API calls of any kind.
// ---------------------------------------------------------------------------
extern "C" void kernel_launch(void* const* d_in, const int* in_sizes, int n_in,
                              void* d_out, int out_size)
{
    const float* yp  = (const float*)d_in[0];
    const float* yf  = (const float*)d_in[1];
    const float* xp  = (const float*)d_in[2];
    const float* xf  = (const float*)d_in[3];
    const float* W1  = (const float*)d_in[4];
    const float* b1  = (const float*)d_in[5];
    const float* g1  = (const float*)d_in[6];
    const float* be1 = (const float*)d_in[7];
    const float* W2  = (const float*)d_in[8];
    const float* b2  = (const float*)d_in[9];
    const float* g2  = (const float*)d_in[10];
    const float* be2 = (const float*)d_in[11];
    const float* W3  = (const float*)d_in[12];
    const float* b3  = (const float*)d_in[13];
    const float* g3  = (const float*)d_in[14];
    const float* be3 = (const float*)d_in[15];
    float* out = (float*)d_out;

    // 1. KNN + interpolation
    knn_kernel<<<dim3(NY / 256, BB), 256>>>(yp, xp);
    interp_kernel<<<NTOT / 8, 256>>>(yf, xf);

    // 2. Layer 1: GEMM (X0 -> H1), BN stats
    sgemm_fused_kernel<false><<<dim3(NTOT / 128, C1 / 128), 256>>>(0, 1, W1, b1, DIMC, C1);
    colsum_kernel<<<NCHUNK, C1>>>(1, C1);
    bnstats_kernel<<<1, C1>>>(g1, be1, C1);

    // 3. Layer 2: GEMM with fused BN1+ReLU on A-load (H1 -> H2), BN stats
    sgemm_fused_kernel<true><<<dim3(NTOT / 128, C2 / 128), 256>>>(1, 2, W2, b2, C1, C2);
    colsum_kernel<<<NCHUNK, C2>>>(2, C2);
    bnstats_kernel<<<1, C2>>>(g2, be2, C2);

    // 4. Layer 3: GEMM with fused BN2+ReLU (H2 -> H3), BN stats
    sgemm_fused_kernel<true><<<dim3(NTOT / 128, C3 / 128), 256>>>(2, 3, W3, b3, C2, C3);
    colsum_kernel<<<NCHUNK, C3>>>(3, C3);
    bnstats_kernel<<<1, C3>>>(g3, be3, C3);

    // 5. BN3+ReLU fused with transpose to [B, C3, NY]
    final_kernel<<<dim3(NTOT / 32, C3 / 32), dim3(32, 8)>>>(out);
}

// round 10
// speedup vs baseline: 3.0343x; 3.0343x over previous
#include <cuda_runtime.h>
#include <cuda_bf16.h>
#include <math.h>
#include <float.h>
#include <stdint.h>

// ---------------------------------------------------------------------------
// Problem constants (fixed shapes)
// ---------------------------------------------------------------------------
#define BB   4
#define NY   16384
#define NX   4096
#define CY   128
#define CX   256
#define DIMC 384          // CY + CX
#define C1   512
#define C2   256
#define C3   128
#define NTOT (BB * NY)    // 65536
#define KNN_EPS 1e-8f
#define BN_EPS  1e-5f

#define NCHUNK 128
#define ROWS_PER_CHUNK (NTOT / NCHUNK)   // 512

// ---------------------------------------------------------------------------
// Device scratch
// ---------------------------------------------------------------------------
__device__ __align__(16) float g_H1[(size_t)NTOT * C1];
__device__ __align__(16) float g_H2[(size_t)NTOT * C2];
__device__ __align__(16) float g_H3[(size_t)NTOT * C3];
__device__ __align__(256) __nv_bfloat16 g_Ahi[(size_t)NTOT * C1];
__device__ __align__(256) __nv_bfloat16 g_Alo[(size_t)NTOT * C1];
__device__ __align__(256) __nv_bfloat16 g_Whi[C1 * DIMC];
__device__ __align__(256) __nv_bfloat16 g_Wlo[C1 * DIMC];
__device__ int   g_idx[NTOT * 3];
__device__ float g_w[NTOT * 3];
__device__ float g_psum[NCHUNK * C1];
__device__ float g_psq[NCHUNK * C1];
__device__ float g_scale[C1];
__device__ float g_shift[C1];

__device__ __forceinline__ float* pick_buf(int s) {
    switch (s) {
        case 1:  return g_H1;
        case 2:  return g_H2;
        default: return g_H3;
    }
}

// ---------------------------------------------------------------------------
// Baseline-PTX helpers (no sm_103a-gated instructions!)
// ---------------------------------------------------------------------------
__device__ __forceinline__ uint32_t smem_u32(const void* p) {
    uint32_t a;
    asm("{ .reg .u64 t; cvta.to.shared.u64 t, %1; cvt.u32.u64 %0, t; }"
        : "=r"(a) : "l"(p));
    return a;
}

#define CP16(dst, src) \
    asm volatile("cp.async.cg.shared.global [%0], [%1], 16;" \
                 :: "r"(dst), "l"((unsigned long long)__cvta_generic_to_global(src)))
#define CP_COMMIT() asm volatile("cp.async.commit_group;")
#define CP_WAIT0()  asm volatile("cp.async.wait_group 0;")
#define CP_WAIT1()  asm volatile("cp.async.wait_group 1;")

#define LDSM4(r0, r1, r2, r3, addr) \
    asm volatile("ldmatrix.sync.aligned.m8n8.x4.shared.b16 {%0,%1,%2,%3}, [%4];" \
                 : "=r"(r0), "=r"(r1), "=r"(r2), "=r"(r3) : "r"(addr))

#define MMA_BF16(c, a, b0, b1) \
    asm volatile("mma.sync.aligned.m16n8k16.row.col.f32.bf16.bf16.f32 " \
                 "{%0,%1,%2,%3}, {%4,%5,%6,%7}, {%8,%9}, {%0,%1,%2,%3};" \
                 : "+f"((c)[0]), "+f"((c)[1]), "+f"((c)[2]), "+f"((c)[3]) \
                 : "r"((a)[0]), "r"((a)[1]), "r"((a)[2]), "r"((a)[3]), \
                   "r"(b0), "r"(b1))

// ---------------------------------------------------------------------------
// KNN — UNCHANGED from the passing round-4 kernel (numerics-critical).
// ---------------------------------------------------------------------------
__global__ void knn_kernel(const float* __restrict__ yp,
                           const float* __restrict__ xp)
{
    __shared__ float4 sx[2048];   // 32 KB
    int b = blockIdx.y;
    const float* xb = xp + (size_t)b * NX * 3;

    int n = blockIdx.x * blockDim.x + threadIdx.x;
    const float* y = yp + ((size_t)b * NY + n) * 3;
    float yx = y[0], yy = y[1], yz = y[2];
    float yn = __fadd_rn(__fadd_rn(__fmul_rn(yx, yx), __fmul_rn(yy, yy)),
                         __fmul_rn(yz, yz));

    float d0 = FLT_MAX, d1 = FLT_MAX, d2 = FLT_MAX;
    int   i0 = 0, i1 = 0, i2 = 0;

    for (int t = 0; t < 2; t++) {
        __syncthreads();
        for (int i = threadIdx.x; i < 2048; i += blockDim.x) {
            const float* p = xb + (size_t)(t * 2048 + i) * 3;
            float a = p[0], c = p[1], e = p[2];
            float xn = __fadd_rn(__fadd_rn(__fmul_rn(a, a), __fmul_rn(c, c)),
                                 __fmul_rn(e, e));
            sx[i] = make_float4(a, c, e, xn);
        }
        __syncthreads();

        int base = t * 2048;
        #pragma unroll 4
        for (int j = 0; j < 2048; j++) {
            float4 q = sx[j];
            float dot = __fmaf_rn(yz, q.z,
                        __fmaf_rn(yy, q.y, __fmul_rn(yx, q.x)));
            float d = __fadd_rn(__fadd_rn(yn, q.w),
                                __fmul_rn(-2.0f, dot));
            if (d < d2) {
                int jj = base + j;
                if (d < d1) {
                    d2 = d1; i2 = i1;
                    if (d < d0) { d1 = d0; i1 = i0; d0 = d; i0 = jj; }
                    else        { d1 = d;  i1 = jj; }
                } else { d2 = d; i2 = jj; }
            }
        }
    }

    float w0 = __fdiv_rn(1.0f, __fadd_rn(d0, KNN_EPS));
    float w1 = __fdiv_rn(1.0f, __fadd_rn(d1, KNN_EPS));
    float w2 = __fdiv_rn(1.0f, __fadd_rn(d2, KNN_EPS));
    float ws = __fadd_rn(__fadd_rn(w0, w1), w2);

    size_t o = ((size_t)b * NY + n) * 3;
    g_idx[o + 0] = i0; g_idx[o + 1] = i1; g_idx[o + 2] = i2;
    g_w[o + 0] = __fdiv_rn(w0, ws);
    g_w[o + 1] = __fdiv_rn(w1, ws);
    g_w[o + 2] = __fdiv_rn(w2, ws);
}

// ---------------------------------------------------------------------------
// Split helper: fp32 -> (hi, lo) bf16
// ---------------------------------------------------------------------------
__device__ __forceinline__ void split_bf16(float v, __nv_bfloat16& h,
                                           __nv_bfloat16& l) {
    h = __float2bfloat16_rn(v);
    l = __float2bfloat16_rn(v - __bfloat162float(h));
}

// ---------------------------------------------------------------------------
// Interpolate + concat, writing SPLIT bf16 A directly (K stride DIMC).
// Same fp32 math as the passing round-4 kernel, then hi/lo split.
// ---------------------------------------------------------------------------
__global__ void interp_split_kernel(const float* __restrict__ yf,
                                    const float* __restrict__ xf)
{
    int warp = (blockIdx.x * blockDim.x + threadIdx.x) >> 5;
    int lane = threadIdx.x & 31;
    if (warp >= NTOT) return;

    int b = warp / NY;
    size_t o = (size_t)warp * 3;
    int i0 = g_idx[o + 0], i1 = g_idx[o + 1], i2 = g_idx[o + 2];
    float w0 = g_w[o + 0], w1 = g_w[o + 1], w2 = g_w[o + 2];

    const float* f0 = xf + ((size_t)b * NX + i0) * CX;
    const float* f1 = xf + ((size_t)b * NX + i1) * CX;
    const float* f2 = xf + ((size_t)b * NX + i2) * CX;
    const float* yrow = yf + (size_t)warp * CY;
    __nv_bfloat16* rh = g_Ahi + (size_t)warp * DIMC;
    __nv_bfloat16* rl = g_Alo + (size_t)warp * DIMC;

    #pragma unroll
    for (int c = lane * 4; c < CY; c += 128) {
        float4 v = *(const float4*)&yrow[c];
        __nv_bfloat16 h[4], l[4];
        split_bf16(v.x, h[0], l[0]); split_bf16(v.y, h[1], l[1]);
        split_bf16(v.z, h[2], l[2]); split_bf16(v.w, h[3], l[3]);
        *(uint2*)&rh[c] = *(uint2*)h;
        *(uint2*)&rl[c] = *(uint2*)l;
    }
    #pragma unroll
    for (int c = lane * 4; c < CX; c += 128) {
        float4 a = *(const float4*)&f0[c];
        float4 b4 = *(const float4*)&f1[c];
        float4 d = *(const float4*)&f2[c];
        float4 r;
        r.x = __fadd_rn(__fadd_rn(__fmul_rn(w0, a.x), __fmul_rn(w1, b4.x)), __fmul_rn(w2, d.x));
        r.y = __fadd_rn(__fadd_rn(__fmul_rn(w0, a.y), __fmul_rn(w1, b4.y)), __fmul_rn(w2, d.y));
        r.z = __fadd_rn(__fadd_rn(__fmul_rn(w0, a.z), __fmul_rn(w1, b4.z)), __fmul_rn(w2, d.z));
        r.w = __fadd_rn(__fadd_rn(__fmul_rn(w0, a.w), __fmul_rn(w1, b4.w)), __fmul_rn(w2, d.w));
        __nv_bfloat16 h[4], l[4];
        split_bf16(r.x, h[0], l[0]); split_bf16(r.y, h[1], l[1]);
        split_bf16(r.z, h[2], l[2]); split_bf16(r.w, h[3], l[3]);
        *(uint2*)&rh[CY + c] = *(uint2*)h;
        *(uint2*)&rl[CY + c] = *(uint2*)l;
    }
}

// ---------------------------------------------------------------------------
// Split kernel: fp32 source -> (hi, lo) bf16.  srcExt != null: external (W);
// else pick_buf(selSrc) (H).  Optional fused BN+ReLU (scale/shift) first.
// dstW selects weight vs activation destination buffers.
// ---------------------------------------------------------------------------
__global__ void split_kernel(const float* srcExt, int selSrc, int dstW,
                             int total4, int C, int fuse)
{
    const float* src = srcExt ? srcExt : pick_buf(selSrc);
    __nv_bfloat16* hi = dstW ? g_Whi : g_Ahi;
    __nv_bfloat16* lo = dstW ? g_Wlo : g_Alo;

    int i = blockIdx.x * blockDim.x + threadIdx.x;
    if (i >= total4) return;
    float4 v = ((const float4*)src)[i];
    if (fuse) {
        int c = (i * 4) % C;
        float4 sc = *(const float4*)&g_scale[c];
        float4 sh = *(const float4*)&g_shift[c];
        v.x = fmaxf(fmaf(v.x, sc.x, sh.x), 0.0f);
        v.y = fmaxf(fmaf(v.y, sc.y, sh.y), 0.0f);
        v.z = fmaxf(fmaf(v.z, sc.z, sh.z), 0.0f);
        v.w = fmaxf(fmaf(v.w, sc.w, sh.w), 0.0f);
    }
    __nv_bfloat16 h[4], l[4];
    split_bf16(v.x, h[0], l[0]); split_bf16(v.y, h[1], l[1]);
    split_bf16(v.z, h[2], l[2]); split_bf16(v.w, h[3], l[3]);
    ((uint2*)hi)[i] = *(uint2*)h;
    ((uint2*)lo)[i] = *(uint2*)l;
}

// ---------------------------------------------------------------------------
// Warp-MMA GEMM, 3xBF16 split: C[M,N] = A*W^T + bias, fp32 accumulate.
// 128x128 block tile, 256 threads (8 warps, 2x4), warp tile 64x32,
// K-chunk 16, 2-stage cp.async pipeline. 48 KB static smem.
// Grid: (N/128, M/128)  — col tiles fast, so A stays L2-resident.
// ---------------------------------------------------------------------------
template <int K>
__global__ void __launch_bounds__(256, 2)
mma_gemm_kernel(int selC, const float* __restrict__ bias, int N)
{
    constexpr int KP  = 24;            // padded k-stride (bf16) -> bank-safe
    constexpr int ARR = 128 * KP;      // elements per (array, stage)
    __shared__ __nv_bfloat16 sm[2 * 4 * ARR];   // 49152 B

    float* C = pick_buf(selC);
    int tid = threadIdx.x;
    int lane = tid & 31, wid = tid >> 5;
    int col0 = blockIdx.x * 128;
    int row0 = blockIdx.y * 128;
    int m_base = (wid >> 2) * 64;
    int n_base = (wid & 3) * 32;

    uint32_t smb = smem_u32(sm);

    // cp.async source/dest (each thread: one 16B chunk per array per stage)
    int ld_row = tid >> 1;
    int ld_c   = tid & 1;
    const __nv_bfloat16* gA0 = g_Ahi + (size_t)(row0 + ld_row) * K + ld_c * 8;
    const __nv_bfloat16* gA1 = g_Alo + (size_t)(row0 + ld_row) * K + ld_c * 8;
    const __nv_bfloat16* gB0 = g_Whi + (size_t)(col0 + ld_row) * K + ld_c * 8;
    const __nv_bfloat16* gB1 = g_Wlo + (size_t)(col0 + ld_row) * K + ld_c * 8;
    uint32_t dst = (uint32_t)(ld_row * KP + ld_c * 8) * 2;

    // ldmatrix per-thread offsets
    uint32_t a_off = (uint32_t)((m_base + (lane & 15)) * KP + (lane >> 4) * 8) * 2;
    uint32_t b_off = (uint32_t)((n_base + (lane & 7) + ((lane >> 4) & 1) * 8) * KP
                                + ((lane >> 3) & 1) * 8) * 2;

    float acc[4][4][4];
    #pragma unroll
    for (int a = 0; a < 4; a++)
        #pragma unroll
        for (int b = 0; b < 4; b++)
            #pragma unroll
            for (int c = 0; c < 4; c++) acc[a][b][c] = 0.0f;

    constexpr int NCH = K / 16;

    // prologue: stage 0
    {
        uint32_t s0 = smb;
        CP16(s0 + 0 * (ARR * 2) + dst, gA0);
        CP16(s0 + 1 * (ARR * 2) + dst, gA1);
        CP16(s0 + 2 * (ARR * 2) + dst, gB0);
        CP16(s0 + 3 * (ARR * 2) + dst, gB1);
        CP_COMMIT();
    }

    for (int ch = 0; ch < NCH; ch++) {
        if (ch + 1 < NCH) {
            int k0 = (ch + 1) * 16;
            uint32_t sb = smb + (uint32_t)(((ch + 1) & 1) * 4) * (ARR * 2);
            CP16(sb + 0 * (ARR * 2) + dst, gA0 + k0);
            CP16(sb + 1 * (ARR * 2) + dst, gA1 + k0);
            CP16(sb + 2 * (ARR * 2) + dst, gB0 + k0);
            CP16(sb + 3 * (ARR * 2) + dst, gB1 + k0);
            CP_COMMIT();
            CP_WAIT1();
        } else {
            CP_WAIT0();
        }
        __syncthreads();

        uint32_t sb = smb + (uint32_t)((ch & 1) * 4) * (ARR * 2);
        uint32_t aH = sb + a_off;
        uint32_t aL = sb + (ARR * 2) + a_off;
        uint32_t bHb = sb + 2 * (ARR * 2) + b_off;
        uint32_t bLb = sb + 3 * (ARR * 2) + b_off;

        // B fragments: 4 n-tiles x {hi,lo}
        uint32_t bh[4][2], bl[4][2];
        #pragma unroll
        for (int bt = 0; bt < 2; bt++) {
            uint32_t r0, r1, r2, r3;
            LDSM4(r0, r1, r2, r3, bHb + (uint32_t)(bt * 16 * KP) * 2);
            bh[2 * bt][0] = r0; bh[2 * bt][1] = r1;
            bh[2 * bt + 1][0] = r2; bh[2 * bt + 1][1] = r3;
            LDSM4(r0, r1, r2, r3, bLb + (uint32_t)(bt * 16 * KP) * 2);
            bl[2 * bt][0] = r0; bl[2 * bt][1] = r1;
            bl[2 * bt + 1][0] = r2; bl[2 * bt + 1][1] = r3;
        }

        #pragma unroll
        for (int mt = 0; mt < 4; mt++) {
            uint32_t ah[4], al[4];
            LDSM4(ah[0], ah[1], ah[2], ah[3], aH + (uint32_t)(mt * 16 * KP) * 2);
            LDSM4(al[0], al[1], al[2], al[3], aL + (uint32_t)(mt * 16 * KP) * 2);
            #pragma unroll
            for (int nt = 0; nt < 4; nt++) {
                MMA_BF16(acc[mt][nt], ah, bh[nt][0], bh[nt][1]);
                MMA_BF16(acc[mt][nt], ah, bl[nt][0], bl[nt][1]);
                MMA_BF16(acc[mt][nt], al, bh[nt][0], bh[nt][1]);
            }
        }
        __syncthreads();
    }

    // epilogue: + bias, fp32 store
    #pragma unroll
    for (int mt = 0; mt < 4; mt++) {
        int r = row0 + m_base + mt * 16 + (lane >> 2);
        #pragma unroll
        for (int nt = 0; nt < 4; nt++) {
            int c = col0 + n_base + nt * 8 + (lane & 3) * 2;
            float2 bv = *(const float2*)&bias[c];
            float2 v0 = make_float2(acc[mt][nt][0] + bv.x, acc[mt][nt][1] + bv.y);
            float2 v1 = make_float2(acc[mt][nt][2] + bv.x, acc[mt][nt][3] + bv.y);
            *(float2*)&C[(size_t)r * N + c] = v0;
            *(float2*)&C[(size_t)(r + 8) * N + c] = v1;
        }
    }
}

// ---------------------------------------------------------------------------
// BN stats — unchanged from round 4.
// ---------------------------------------------------------------------------
__global__ void colsum_kernel(int selH, int C)
{
    const float* H = pick_buf(selH);
    int c = threadIdx.x;
    int chunk = blockIdx.x;
    const float* p = H + (size_t)chunk * ROWS_PER_CHUNK * C;
    float s = 0.0f, ss = 0.0f;
    for (int r = 0; r < ROWS_PER_CHUNK; r++) {
        float v = p[(size_t)r * C + c];
        s += v; ss = fmaf(v, v, ss);
    }
    g_psum[chunk * C + c] = s;
    g_psq[chunk * C + c]  = ss;
}

__global__ void bnstats_kernel(const float* __restrict__ g,
                               const float* __restrict__ be, int C)
{
    int c = threadIdx.x;
    float s = 0.0f, ss = 0.0f;
    for (int j = 0; j < NCHUNK; j++) {
        s += g_psum[j * C + c];
        ss += g_psq[j * C + c];
    }
    const float invN = 1.0f / (float)NTOT;
    float mu  = s * invN;
    float var = ss * invN - mu * mu;
    float inv = rsqrtf(var + BN_EPS);
    float a = g[c] * inv;
    g_scale[c] = a;
    g_shift[c] = be[c] - mu * a;
}

// ---------------------------------------------------------------------------
// Final: affine + ReLU + transpose [N, C3] -> [B, C3, NY] — unchanged.
// ---------------------------------------------------------------------------
__global__ void final_kernel(float* __restrict__ out)
{
    __shared__ float tile[32][33];
    int nb = blockIdx.x;
    int cb = blockIdx.y;
    int lx = threadIdx.x;    // 32
    int ly = threadIdx.y;    // 8

    int c = cb * 32 + lx;
    float a = g_scale[c], sh = g_shift[c];
    #pragma unroll
    for (int s = 0; s < 4; s++) {
        int r = nb * 32 + ly + s * 8;
        float v = fmaf(g_H3[(size_t)r * C3 + c], a, sh);
        tile[ly + s * 8][lx] = fmaxf(v, 0.0f);
    }
    __syncthreads();

    int gn = nb * 32 + lx;
    int b  = gn / NY;
    int nn = gn % NY;
    #pragma unroll
    for (int s = 0; s < 4; s++) {
        int cc = cb * 32 + ly + s * 8;
        out[((size_t)b * C3 + cc) * NY + nn] = tile[lx][ly + s * 8];
    }
}

// ---------------------------------------------------------------------------
// Launch: kernel launches ONLY.
// ---------------------------------------------------------------------------
extern "C" void kernel_launch(void* const* d_in, const int* in_sizes, int n_in,
                              void* d_out, int out_size)
{
    const float* yp  = (const float*)d_in[0];
    const float* yf  = (const float*)d_in[1];
    const float* xp  = (const float*)d_in[2];
    const float* xf  = (const float*)d_in[3];
    const float* W1  = (const float*)d_in[4];
    const float* b1  = (const float*)d_in[5];
    const float* g1  = (const float*)d_in[6];
    const float* be1 = (const float*)d_in[7];
    const float* W2  = (const float*)d_in[8];
    const float* b2  = (const float*)d_in[9];
    const float* g2  = (const float*)d_in[10];
    const float* be2 = (const float*)d_in[11];
    const float* W3  = (const float*)d_in[12];
    const float* b3  = (const float*)d_in[13];
    const float* g3  = (const float*)d_in[14];
    const float* be3 = (const float*)d_in[15];
    float* out = (float*)d_out;

    // 1. KNN + interpolation (interp writes split bf16 A for layer 1)
    knn_kernel<<<dim3(NY / 256, BB), 256>>>(yp, xp);
    interp_split_kernel<<<NTOT / 8, 256>>>(yf, xf);

    // 2. Layer 1
    split_kernel<<<(C1 * DIMC / 4 + 255) / 256, 256>>>(W1, 0, 1, C1 * DIMC / 4, DIMC, 0);
    mma_gemm_kernel<DIMC><<<dim3(C1 / 128, NTOT / 128), 256>>>(1, b1, C1);
    colsum_kernel<<<NCHUNK, C1>>>(1, C1);
    bnstats_kernel<<<1, C1>>>(g1, be1, C1);

    // 3. Layer 2 (split fuses BN1+ReLU)
    split_kernel<<<(NTOT * C1 / 4 + 255) / 256, 256>>>(nullptr, 1, 0, NTOT * C1 / 4, C1, 1);
    split_kernel<<<(C2 * C1 / 4 + 255) / 256, 256>>>(W2, 0, 1, C2 * C1 / 4, C1, 0);
    mma_gemm_kernel<C1><<<dim3(C2 / 128, NTOT / 128), 256>>>(2, b2, C2);
    colsum_kernel<<<NCHUNK, C2>>>(2, C2);
    bnstats_kernel<<<1, C2>>>(g2, be2, C2);

    // 4. Layer 3 (split fuses BN2+ReLU)
    split_kernel<<<(NTOT * C2 / 4 + 255) / 256, 256>>>(nullptr, 2, 0, NTOT * C2 / 4, C2, 1);
    split_kernel<<<(C3 * C2 / 4 + 255) / 256, 256>>>(W3, 0, 1, C3 * C2 / 4, C2, 0);
    mma_gemm_kernel<C2><<<dim3(C3 / 128, NTOT / 128), 256>>>(3, b3, C3);
    colsum_kernel<<<NCHUNK, C3>>>(3, C3);
    bnstats_kernel<<<1, C3>>>(g3, be3, C3);

    // 5. BN3+ReLU fused with transpose to [B, C3, NY]
    final_kernel<<<dim3(NTOT / 32, C3 / 32), dim3(32, 8)>>>(out);
}

// round 14
// speedup vs baseline: 3.0651x; 1.0101x over previous
#include <cuda_runtime.h>
#include <cuda_bf16.h>
#include <math.h>
#include <float.h>
#include <stdint.h>

// ---------------------------------------------------------------------------
// Problem constants (fixed shapes)
// ---------------------------------------------------------------------------
#define BB   4
#define NY   16384
#define NX   4096
#define CY   128
#define CX   256
#define DIMC 384          // CY + CX
#define C1   512
#define C2   256
#define C3   128
#define NTOT (BB * NY)    // 65536
#define KNN_EPS 1e-8f
#define BN_EPS  1e-5f

#define NCHUNK 256
#define ROWS_PER_CHUNK (NTOT / NCHUNK)   // 256

// ---------------------------------------------------------------------------
// Device scratch
// ---------------------------------------------------------------------------
__device__ __align__(16) float g_H1[(size_t)NTOT * C1];
__device__ __align__(16) float g_H2[(size_t)NTOT * C2];
__device__ __align__(16) float g_H3[(size_t)NTOT * C3];
__device__ __align__(256) __nv_bfloat16 g_Ahi[(size_t)NTOT * C1];
__device__ __align__(256) __nv_bfloat16 g_Alo[(size_t)NTOT * C1];
__device__ __align__(256) __nv_bfloat16 g_Whi[C1 * DIMC];
__device__ __align__(256) __nv_bfloat16 g_Wlo[C1 * DIMC];
__device__ int   g_idx[NTOT * 3];
__device__ float g_w[NTOT * 3];
__device__ float g_psum[NCHUNK * C1];
__device__ float g_psq[NCHUNK * C1];
__device__ float g_scale[C1];
__device__ float g_shift[C1];

__device__ __forceinline__ float* pick_buf(int s) {
    switch (s) {
        case 1:  return g_H1;
        case 2:  return g_H2;
        default: return g_H3;
    }
}

// ---------------------------------------------------------------------------
// Baseline-PTX helpers (compute_103-safe; no sm_103a-gated instructions)
// ---------------------------------------------------------------------------
__device__ __forceinline__ uint32_t smem_u32(const void* p) {
    uint32_t a;
    asm("{ .reg .u64 t; cvta.to.shared.u64 t, %1; cvt.u32.u64 %0, t; }"
        : "=r"(a) : "l"(p));
    return a;
}

#define CP16(dst, src) \
    asm volatile("cp.async.cg.shared.global [%0], [%1], 16;" \
                 :: "r"(dst), "l"((unsigned long long)__cvta_generic_to_global(src)))
#define CP_COMMIT() asm volatile("cp.async.commit_group;")
#define CP_WAIT0()  asm volatile("cp.async.wait_group 0;")
#define CP_WAIT1()  asm volatile("cp.async.wait_group 1;")

#define LDSM4(r0, r1, r2, r3, addr) \
    asm volatile("ldmatrix.sync.aligned.m8n8.x4.shared.b16 {%0,%1,%2,%3}, [%4];" \
                 : "=r"(r0), "=r"(r1), "=r"(r2), "=r"(r3) : "r"(addr))

#define MMA_BF16(c, a, b0, b1) \
    asm volatile("mma.sync.aligned.m16n8k16.row.col.f32.bf16.bf16.f32 " \
                 "{%0,%1,%2,%3}, {%4,%5,%6,%7}, {%8,%9}, {%0,%1,%2,%3};" \
                 : "+f"((c)[0]), "+f"((c)[1]), "+f"((c)[2]), "+f"((c)[3]) \
                 : "r"((a)[0]), "r"((a)[1]), "r"((a)[2]), "r"((a)[3]), \
                   "r"(b0), "r"(b1))

// ---------------------------------------------------------------------------
// KNN — UNCHANGED from the passing kernel (numerics-critical).
// ---------------------------------------------------------------------------
__global__ void knn_kernel(const float* __restrict__ yp,
                           const float* __restrict__ xp)
{
    __shared__ float4 sx[2048];   // 32 KB
    int b = blockIdx.y;
    const float* xb = xp + (size_t)b * NX * 3;

    int n = blockIdx.x * blockDim.x + threadIdx.x;
    const float* y = yp + ((size_t)b * NY + n) * 3;
    float yx = y[0], yy = y[1], yz = y[2];
    float yn = __fadd_rn(__fadd_rn(__fmul_rn(yx, yx), __fmul_rn(yy, yy)),
                         __fmul_rn(yz, yz));

    float d0 = FLT_MAX, d1 = FLT_MAX, d2 = FLT_MAX;
    int   i0 = 0, i1 = 0, i2 = 0;

    for (int t = 0; t < 2; t++) {
        __syncthreads();
        for (int i = threadIdx.x; i < 2048; i += blockDim.x) {
            const float* p = xb + (size_t)(t * 2048 + i) * 3;
            float a = p[0], c = p[1], e = p[2];
            float xn = __fadd_rn(__fadd_rn(__fmul_rn(a, a), __fmul_rn(c, c)),
                                 __fmul_rn(e, e));
            sx[i] = make_float4(a, c, e, xn);
        }
        __syncthreads();

        int base = t * 2048;
        #pragma unroll 4
        for (int j = 0; j < 2048; j++) {
            float4 q = sx[j];
            float dot = __fmaf_rn(yz, q.z,
                        __fmaf_rn(yy, q.y, __fmul_rn(yx, q.x)));
            float d = __fadd_rn(__fadd_rn(yn, q.w),
                                __fmul_rn(-2.0f, dot));
            if (d < d2) {
                int jj = base + j;
                if (d < d1) {
                    d2 = d1; i2 = i1;
                    if (d < d0) { d1 = d0; i1 = i0; d0 = d; i0 = jj; }
                    else        { d1 = d;  i1 = jj; }
                } else { d2 = d; i2 = jj; }
            }
        }
    }

    float w0 = __fdiv_rn(1.0f, __fadd_rn(d0, KNN_EPS));
    float w1 = __fdiv_rn(1.0f, __fadd_rn(d1, KNN_EPS));
    float w2 = __fdiv_rn(1.0f, __fadd_rn(d2, KNN_EPS));
    float ws = __fadd_rn(__fadd_rn(w0, w1), w2);

    size_t o = ((size_t)b * NY + n) * 3;
    g_idx[o + 0] = i0; g_idx[o + 1] = i1; g_idx[o + 2] = i2;
    g_w[o + 0] = __fdiv_rn(w0, ws);
    g_w[o + 1] = __fdiv_rn(w1, ws);
    g_w[o + 2] = __fdiv_rn(w2, ws);
}

// ---------------------------------------------------------------------------
// Split helper: fp32 -> (hi, lo) bf16
// ---------------------------------------------------------------------------
__device__ __forceinline__ void split_bf16(float v, __nv_bfloat16& h,
                                           __nv_bfloat16& l) {
    h = __float2bfloat16_rn(v);
    l = __float2bfloat16_rn(v - __bfloat162float(h));
}

// ---------------------------------------------------------------------------
// Interpolate + concat, writing SPLIT bf16 A directly — unchanged.
// ---------------------------------------------------------------------------
__global__ void interp_split_kernel(const float* __restrict__ yf,
                                    const float* __restrict__ xf)
{
    int warp = (blockIdx.x * blockDim.x + threadIdx.x) >> 5;
    int lane = threadIdx.x & 31;
    if (warp >= NTOT) return;

    int b = warp / NY;
    size_t o = (size_t)warp * 3;
    int i0 = g_idx[o + 0], i1 = g_idx[o + 1], i2 = g_idx[o + 2];
    float w0 = g_w[o + 0], w1 = g_w[o + 1], w2 = g_w[o + 2];

    const float* f0 = xf + ((size_t)b * NX + i0) * CX;
    const float* f1 = xf + ((size_t)b * NX + i1) * CX;
    const float* f2 = xf + ((size_t)b * NX + i2) * CX;
    const float* yrow = yf + (size_t)warp * CY;
    __nv_bfloat16* rh = g_Ahi + (size_t)warp * DIMC;
    __nv_bfloat16* rl = g_Alo + (size_t)warp * DIMC;

    #pragma unroll
    for (int c = lane * 4; c < CY; c += 128) {
        float4 v = *(const float4*)&yrow[c];
        __nv_bfloat16 h[4], l[4];
        split_bf16(v.x, h[0], l[0]); split_bf16(v.y, h[1], l[1]);
        split_bf16(v.z, h[2], l[2]); split_bf16(v.w, h[3], l[3]);
        *(uint2*)&rh[c] = *(uint2*)h;
        *(uint2*)&rl[c] = *(uint2*)l;
    }
    #pragma unroll
    for (int c = lane * 4; c < CX; c += 128) {
        float4 a = *(const float4*)&f0[c];
        float4 b4 = *(const float4*)&f1[c];
        float4 d = *(const float4*)&f2[c];
        float4 r;
        r.x = __fadd_rn(__fadd_rn(__fmul_rn(w0, a.x), __fmul_rn(w1, b4.x)), __fmul_rn(w2, d.x));
        r.y = __fadd_rn(__fadd_rn(__fmul_rn(w0, a.y), __fmul_rn(w1, b4.y)), __fmul_rn(w2, d.y));
        r.z = __fadd_rn(__fadd_rn(__fmul_rn(w0, a.z), __fmul_rn(w1, b4.z)), __fmul_rn(w2, d.z));
        r.w = __fadd_rn(__fadd_rn(__fmul_rn(w0, a.w), __fmul_rn(w1, b4.w)), __fmul_rn(w2, d.w));
        __nv_bfloat16 h[4], l[4];
        split_bf16(r.x, h[0], l[0]); split_bf16(r.y, h[1], l[1]);
        split_bf16(r.z, h[2], l[2]); split_bf16(r.w, h[3], l[3]);
        *(uint2*)&rh[CY + c] = *(uint2*)h;
        *(uint2*)&rl[CY + c] = *(uint2*)l;
    }
}

// ---------------------------------------------------------------------------
// Split kernel (optionally fused BN+ReLU) — unchanged.
// ---------------------------------------------------------------------------
__global__ void split_kernel(const float* srcExt, int selSrc, int dstW,
                             int total4, int C, int fuse)
{
    const float* src = srcExt ? srcExt : pick_buf(selSrc);
    __nv_bfloat16* hi = dstW ? g_Whi : g_Ahi;
    __nv_bfloat16* lo = dstW ? g_Wlo : g_Alo;

    int i = blockIdx.x * blockDim.x + threadIdx.x;
    if (i >= total4) return;
    float4 v = ((const float4*)src)[i];
    if (fuse) {
        int c = (i * 4) % C;
        float4 sc = *(const float4*)&g_scale[c];
        float4 sh = *(const float4*)&g_shift[c];
        v.x = fmaxf(fmaf(v.x, sc.x, sh.x), 0.0f);
        v.y = fmaxf(fmaf(v.y, sc.y, sh.y), 0.0f);
        v.z = fmaxf(fmaf(v.z, sc.z, sh.z), 0.0f);
        v.w = fmaxf(fmaf(v.w, sc.w, sh.w), 0.0f);
    }
    __nv_bfloat16 h[4], l[4];
    split_bf16(v.x, h[0], l[0]); split_bf16(v.y, h[1], l[1]);
    split_bf16(v.z, h[2], l[2]); split_bf16(v.w, h[3], l[3]);
    ((uint2*)hi)[i] = *(uint2*)h;
    ((uint2*)lo)[i] = *(uint2*)l;
}

// ---------------------------------------------------------------------------
// Warp-MMA GEMM, 3xBF16 split, 4-stage cp.async pipeline.
// 128x128 block tile, 256 threads (8 warps, 2x4), warp tile 64x32, K-chunk 16.
// One __syncthreads per chunk; B fragments prefetched one chunk ahead.
// Dynamic smem: 4 stages x 4 arrays x 128x24 bf16 = 96 KB.
// ---------------------------------------------------------------------------
#define KP     24
#define ARRB   (128 * KP * 2)        // 6144 B per array
#define STAGEB (4 * ARRB)            // 24576 B per stage
#define GSMEM  (4 * STAGEB)          // 98304 B total

template <int K>
__global__ void __launch_bounds__(256, 2)
mma_gemm_kernel(int selC, const float* __restrict__ bias, int N)
{
    extern __shared__ __nv_bfloat16 smdyn[];
    uint32_t smb = smem_u32(smdyn);

    float* C = pick_buf(selC);
    int tid = threadIdx.x;
    int lane = tid & 31, wid = tid >> 5;
    int col0 = blockIdx.x * 128;
    int row0 = blockIdx.y * 128;
    int m_base = (wid >> 2) * 64;
    int n_base = (wid & 3) * 32;

    // cp.async addressing: each thread does one 16B chunk per array per stage
    int ld_row = tid >> 1;
    int ld_c   = tid & 1;
    const __nv_bfloat16* gA0 = g_Ahi + (size_t)(row0 + ld_row) * K + ld_c * 8;
    const __nv_bfloat16* gA1 = g_Alo + (size_t)(row0 + ld_row) * K + ld_c * 8;
    const __nv_bfloat16* gB0 = g_Whi + (size_t)(col0 + ld_row) * K + ld_c * 8;
    const __nv_bfloat16* gB1 = g_Wlo + (size_t)(col0 + ld_row) * K + ld_c * 8;
    uint32_t dst = (uint32_t)(ld_row * KP + ld_c * 8) * 2;

    // ldmatrix per-thread offsets (within an array)
    uint32_t a_off = (uint32_t)((m_base + (lane & 15)) * KP + (lane >> 4) * 8) * 2;
    uint32_t b_off = (uint32_t)((n_base + (lane & 7) + ((lane >> 4) & 1) * 8) * KP
                                + ((lane >> 3) & 1) * 8) * 2;

    float acc[4][4][4];
    #pragma unroll
    for (int a = 0; a < 4; a++)
        #pragma unroll
        for (int b = 0; b < 4; b++)
            #pragma unroll
            for (int c = 0; c < 4; c++) acc[a][b][c] = 0.0f;

    constexpr int NCH = K / 16;

    // stage fill
    #define CP_STAGE(ch) do {                                            \
        uint32_t _sb = smb + (uint32_t)(((ch) & 3) * STAGEB) + dst;      \
        int _k0 = (ch) * 16;                                             \
        CP16(_sb + 0 * ARRB, gA0 + _k0);                                 \
        CP16(_sb + 1 * ARRB, gA1 + _k0);                                 \
        CP16(_sb + 2 * ARRB, gB0 + _k0);                                 \
        CP16(_sb + 3 * ARRB, gB1 + _k0);                                 \
        CP_COMMIT();                                                     \
    } while (0)

    // B fragment loader from stage s into (BH, BL)
    #define LOAD_B(BH, BL, s) do {                                       \
        uint32_t _bb = smb + (uint32_t)((s) * STAGEB);                   \
        uint32_t _bh = _bb + 2 * ARRB + b_off;                           \
        uint32_t _bl = _bb + 3 * ARRB + b_off;                           \
        uint32_t _r0, _r1, _r2, _r3;                                     \
        LDSM4(_r0, _r1, _r2, _r3, _bh);                                  \
        (BH)[0][0] = _r0; (BH)[0][1] = _r1; (BH)[1][0] = _r2; (BH)[1][1] = _r3; \
        LDSM4(_r0, _r1, _r2, _r3, _bh + (uint32_t)(16 * KP * 2));        \
        (BH)[2][0] = _r0; (BH)[2][1] = _r1; (BH)[3][0] = _r2; (BH)[3][1] = _r3; \
        LDSM4(_r0, _r1, _r2, _r3, _bl);                                  \
        (BL)[0][0] = _r0; (BL)[0][1] = _r1; (BL)[1][0] = _r2; (BL)[1][1] = _r3; \
        LDSM4(_r0, _r1, _r2, _r3, _bl + (uint32_t)(16 * KP * 2));        \
        (BL)[2][0] = _r0; (BL)[2][1] = _r1; (BL)[3][0] = _r2; (BL)[3][1] = _r3; \
    } while (0)

    // one pipeline step: consume chunk ch with (CH,CL), prefetch ch+1 into (NH,NL)
    #define STEP(ch, CH, CL, NH, NL) do {                                \
        if ((ch) + 3 < NCH) CP_STAGE((ch) + 3);                          \
        if ((ch) + 1 < NCH) LOAD_B(NH, NL, ((ch) + 1) & 3);              \
        uint32_t _ab = smb + (uint32_t)(((ch) & 3) * STAGEB);            \
        uint32_t _aH = _ab + a_off;                                      \
        uint32_t _aL = _ab + ARRB + a_off;                               \
        _Pragma("unroll")                                                \
        for (int mt = 0; mt < 4; mt++) {                                 \
            uint32_t ah[4], al[4];                                       \
            LDSM4(ah[0], ah[1], ah[2], ah[3], _aH + (uint32_t)(mt * 16 * KP * 2)); \
            LDSM4(al[0], al[1], al[2], al[3], _aL + (uint32_t)(mt * 16 * KP * 2)); \
            _Pragma("unroll")                                            \
            for (int nt = 0; nt < 4; nt++) {                             \
                MMA_BF16(acc[mt][nt], ah, (CH)[nt][0], (CH)[nt][1]);     \
                MMA_BF16(acc[mt][nt], ah, (CL)[nt][0], (CL)[nt][1]);     \
                MMA_BF16(acc[mt][nt], al, (CH)[nt][0], (CH)[nt][1]);     \
            }                                                            \
        }                                                                \
        if ((ch) + 3 < NCH) CP_WAIT1(); else CP_WAIT0();                 \
        __syncthreads();                                                 \
    } while (0)

    // prologue: fill stages 0..2; certify chunks 0 and 1
    CP_STAGE(0); CP_STAGE(1); CP_STAGE(2);
    CP_WAIT1();
    __syncthreads();

    uint32_t bh0[4][2], bl0[4][2], bh1[4][2], bl1[4][2];
    LOAD_B(bh0, bl0, 0);

    #pragma unroll 1
    for (int ch = 0; ch < NCH; ch += 2) {
        STEP(ch,     bh0, bl0, bh1, bl1);
        STEP(ch + 1, bh1, bl1, bh0, bl0);
    }

    // epilogue: + bias, fp32 store
    #pragma unroll
    for (int mt = 0; mt < 4; mt++) {
        int r = row0 + m_base + mt * 16 + (lane >> 2);
        #pragma unroll
        for (int nt = 0; nt < 4; nt++) {
            int c = col0 + n_base + nt * 8 + (lane & 3) * 2;
            float2 bv = *(const float2*)&bias[c];
            float2 v0 = make_float2(acc[mt][nt][0] + bv.x, acc[mt][nt][1] + bv.y);
            float2 v1 = make_float2(acc[mt][nt][2] + bv.x, acc[mt][nt][3] + bv.y);
            *(float2*)&C[(size_t)r * N + c] = v0;
            *(float2*)&C[(size_t)(r + 8) * N + c] = v1;
        }
    }
    #undef STEP
    #undef LOAD_B
    #undef CP_STAGE
}

// ---------------------------------------------------------------------------
// BN stats — NCHUNK=256 for more CTA parallelism.
// ---------------------------------------------------------------------------
__global__ void colsum_kernel(int selH, int C)
{
    const float* H = pick_buf(selH);
    int c = threadIdx.x;
    int chunk = blockIdx.x;
    const float* p = H + (size_t)chunk * ROWS_PER_CHUNK * C;
    float s = 0.0f, ss = 0.0f;
    for (int r = 0; r < ROWS_PER_CHUNK; r++) {
        float v = p[(size_t)r * C + c];
        s += v; ss = fmaf(v, v, ss);
    }
    g_psum[chunk * C + c] = s;
    g_psq[chunk * C + c]  = ss;
}

__global__ void bnstats_kernel(const float* __restrict__ g,
                               const float* __restrict__ be, int C)
{
    int c = threadIdx.x;
    float s = 0.0f, ss = 0.0f;
    #pragma unroll 8
    for (int j = 0; j < NCHUNK; j++) {
        s += g_psum[j * C + c];
        ss += g_psq[j * C + c];
    }
    const float invN = 1.0f / (float)NTOT;
    float mu  = s * invN;
    float var = ss * invN - mu * mu;
    float inv = rsqrtf(var + BN_EPS);
    float a = g[c] * inv;
    g_scale[c] = a;
    g_shift[c] = be[c] - mu * a;
}

// ---------------------------------------------------------------------------
// Final: affine + ReLU + transpose [N, C3] -> [B, C3, NY] — unchanged.
// ---------------------------------------------------------------------------
__global__ void final_kernel(float* __restrict__ out)
{
    __shared__ float tile[32][33];
    int nb = blockIdx.x;
    int cb = blockIdx.y;
    int lx = threadIdx.x;    // 32
    int ly = threadIdx.y;    // 8

    int c = cb * 32 + lx;
    float a = g_scale[c], sh = g_shift[c];
    #pragma unroll
    for (int s = 0; s < 4; s++) {
        int r = nb * 32 + ly + s * 8;
        float v = fmaf(g_H3[(size_t)r * C3 + c], a, sh);
        tile[ly + s * 8][lx] = fmaxf(v, 0.0f);
    }
    __syncthreads();

    int gn = nb * 32 + lx;
    int b  = gn / NY;
    int nn = gn % NY;
    #pragma unroll
    for (int s = 0; s < 4; s++) {
        int cc = cb * 32 + ly + s * 8;
        out[((size_t)b * C3 + cc) * NY + nn] = tile[lx][ly + s * 8];
    }
}

// ---------------------------------------------------------------------------
// Launch
// ---------------------------------------------------------------------------
extern "C" void kernel_launch(void* const* d_in, const int* in_sizes, int n_in,
                              void* d_out, int out_size)
{
    const float* yp  = (const float*)d_in[0];
    const float* yf  = (const float*)d_in[1];
    const float* xp  = (const float*)d_in[2];
    const float* xf  = (const float*)d_in[3];
    const float* W1  = (const float*)d_in[4];
    const float* b1  = (const float*)d_in[5];
    const float* g1  = (const float*)d_in[6];
    const float* be1 = (const float*)d_in[7];
    const float* W2  = (const float*)d_in[8];
    const float* b2  = (const float*)d_in[9];
    const float* g2  = (const float*)d_in[10];
    const float* be2 = (const float*)d_in[11];
    const float* W3  = (const float*)d_in[12];
    const float* b3  = (const float*)d_in[13];
    const float* g3  = (const float*)d_in[14];
    const float* be3 = (const float*)d_in[15];
    float* out = (float*)d_out;

    cudaFuncSetAttribute(mma_gemm_kernel<DIMC>,
                         cudaFuncAttributeMaxDynamicSharedMemorySize, GSMEM);
    cudaFuncSetAttribute(mma_gemm_kernel<C1>,
                         cudaFuncAttributeMaxDynamicSharedMemorySize, GSMEM);
    cudaFuncSetAttribute(mma_gemm_kernel<C2>,
                         cudaFuncAttributeMaxDynamicSharedMemorySize, GSMEM);

    // 1. KNN + interpolation (interp writes split bf16 A for layer 1)
    knn_kernel<<<dim3(NY / 256, BB), 256>>>(yp, xp);
    interp_split_kernel<<<NTOT / 8, 256>>>(yf, xf);

    // 2. Layer 1
    split_kernel<<<(C1 * DIMC / 4 + 255) / 256, 256>>>(W1, 0, 1, C1 * DIMC / 4, DIMC, 0);
    mma_gemm_kernel<DIMC><<<dim3(C1 / 128, NTOT / 128), 256, GSMEM>>>(1, b1, C1);
    colsum_kernel<<<NCHUNK, C1>>>(1, C1);
    bnstats_kernel<<<1, C1>>>(g1, be1, C1);

    // 3. Layer 2 (split fuses BN1+ReLU)
    split_kernel<<<(NTOT * C1 / 4 + 255) / 256, 256>>>(nullptr, 1, 0, NTOT * C1 / 4, C1, 1);
    split_kernel<<<(C2 * C1 / 4 + 255) / 256, 256>>>(W2, 0, 1, C2 * C1 / 4, C1, 0);
    mma_gemm_kernel<C1><<<dim3(C2 / 128, NTOT / 128), 256, GSMEM>>>(2, b2, C2);
    colsum_kernel<<<NCHUNK, C2>>>(2, C2);
    bnstats_kernel<<<1, C2>>>(g2, be2, C2);

    // 4. Layer 3 (split fuses BN2+ReLU)
    split_kernel<<<(NTOT * C2 / 4 + 255) / 256, 256>>>(nullptr, 2, 0, NTOT * C2 / 4, C2, 1);
    split_kernel<<<(C3 * C2 / 4 + 255) / 256, 256>>>(W3, 0, 1, C3 * C2 / 4, C2, 0);
    mma_gemm_kernel<C2><<<dim3(C3 / 128, NTOT / 128), 256, GSMEM>>>(3, b3, C3);
    colsum_kernel<<<NCHUNK, C3>>>(3, C3);
    bnstats_kernel<<<1, C3>>>(g3, be3, C3);

    // 5. BN3+ReLU fused with transpose to [B, C3, NY]
    final_kernel<<<dim3(NTOT / 32, C3 / 32), dim3(32, 8)>>>(out);
}